// round 11
// baseline (speedup 1.0000x reference)
#include <cuda_runtime.h>
#include <math.h>

#define NB  2
#define CH  288
#define HP  4096
#define KPP 1024
#define NH  9
#define DH  32
#define TQ  16

typedef unsigned long long ull;

// ---- packed f32x2 FMA (sm_103a FFMA2; PTX-only path) ----
#define FMA2(d, a, b) asm("fma.rn.f32x2 %0, %1, %2, %0;" : "+l"(d) : "l"(a), "l"(b))
#define PK2(d, lo, hi) asm("mov.b64 %0, {%1, %2};" : "=l"(d) : "r"(__float_as_uint(lo)), "r"(__float_as_uint(hi)))
#define UPK2(lo, hi, v) do { unsigned int _ul, _uh; \
    asm("mov.b64 {%0, %1}, %2;" : "=r"(_ul), "=r"(_uh) : "l"(v)); \
    (lo) = __uint_as_float(_ul); (hi) = __uint_as_float(_uh); } while (0)

// ---- cp.async helpers ----
#define CP_ASYNC16(dst_u32, src_ptr) \
    asm volatile("cp.async.cg.shared.global [%0], [%1], 16;" :: "r"(dst_u32), "l"(src_ptr))
#define CP_COMMIT() asm volatile("cp.async.commit_group;")
#define CP_WAIT(n)  asm volatile("cp.async.wait_group %0;" :: "n"(n))

// ---------------- device scratch ----------------
__device__ float g_Q   [NB*HP*CH];
__device__ float g_KTd [NB*NH*DH*KPP];   // k[n][m][dd][kp]
__device__ float g_V   [NB*KPP*CH];
__device__ float g_O   [NB*HP*CH];
__device__ float g_PFX [NH*64*32*DH];    // pfx[m][a][d][kk]
__device__ float g_PFY [NH*64*32*DH];    // pfy[m][a][d][kk]
__device__ float g_EX  [NB*NH*HP*32];    // ex[n][m][q][wk]
__device__ float g_EY  [NB*NH*HP*32];    // ey[n][m][q][hk]
__device__ float g_Atn [NB*HP*KPP];
__device__ float g_ctxp[NB*32*CH];

// =================================================================================
// Kernel 1: Q/K/V projections.  BM=128 x BN=96, BK=32, 256 threads, 8x6 (FFMA2).
// =================================================================================
__global__ __launch_bounds__(256) void qkv_kernel(
    const float* __restrict__ x,
    const float* __restrict__ Wq,
    const float* __restrict__ Wk,
    const float* __restrict__ Wv)
{
    int which = blockIdx.z >> 1;
    int n     = blockIdx.z & 1;
    int rows  = (which == 0) ? HP : KPP;
    int p0    = blockIdx.x * 128;
    if (p0 >= rows) return;
    int o0    = blockIdx.y * 96;

    const float* W = (which == 0) ? Wq : (which == 1 ? Wk : Wv);
    const float* xb = x + (size_t)n*CH*HP;

    __shared__ float As[32][132];
    __shared__ float Bs[32][96];

    int t  = threadIdx.x;
    int tx = t & 15, ty = t >> 4;
    ull acc2[8][3] = {};

    for (int c0 = 0; c0 < CH; c0 += 32) {
#pragma unroll
        for (int i = 0; i < 16; i++) {
            int idx = t + i*256;
            int c = idx >> 7, pix = idx & 127;
            int row = p0 + pix;
            int pixel = (which == 0) ? row : (((row >> 5) << 7) | ((row & 31) << 1));
            As[c][pix] = xb[(size_t)(c0 + c)*HP + pixel];
        }
#pragma unroll
        for (int i = 0; i < 12; i++) {
            int idx = t + i*256;
            int o = idx >> 5, c = idx & 31;
            Bs[c][o] = W[(size_t)(o0 + o)*CH + c0 + c];
        }
        __syncthreads();
#pragma unroll
        for (int c = 0; c < 32; c++) {
            float4 a0 = *(const float4*)&As[c][ty*8];
            float4 a1 = *(const float4*)&As[c][ty*8 + 4];
            ull b0 = *(const ull*)&Bs[c][tx*6];
            ull b1 = *(const ull*)&Bs[c][tx*6 + 2];
            ull b2 = *(const ull*)&Bs[c][tx*6 + 4];
            ull pa;
            PK2(pa, a0.x, a0.x); FMA2(acc2[0][0],pa,b0); FMA2(acc2[0][1],pa,b1); FMA2(acc2[0][2],pa,b2);
            PK2(pa, a0.y, a0.y); FMA2(acc2[1][0],pa,b0); FMA2(acc2[1][1],pa,b1); FMA2(acc2[1][2],pa,b2);
            PK2(pa, a0.z, a0.z); FMA2(acc2[2][0],pa,b0); FMA2(acc2[2][1],pa,b1); FMA2(acc2[2][2],pa,b2);
            PK2(pa, a0.w, a0.w); FMA2(acc2[3][0],pa,b0); FMA2(acc2[3][1],pa,b1); FMA2(acc2[3][2],pa,b2);
            PK2(pa, a1.x, a1.x); FMA2(acc2[4][0],pa,b0); FMA2(acc2[4][1],pa,b1); FMA2(acc2[4][2],pa,b2);
            PK2(pa, a1.y, a1.y); FMA2(acc2[5][0],pa,b0); FMA2(acc2[5][1],pa,b1); FMA2(acc2[5][2],pa,b2);
            PK2(pa, a1.z, a1.z); FMA2(acc2[6][0],pa,b0); FMA2(acc2[6][1],pa,b1); FMA2(acc2[6][2],pa,b2);
            PK2(pa, a1.w, a1.w); FMA2(acc2[7][0],pa,b0); FMA2(acc2[7][1],pa,b1); FMA2(acc2[7][2],pa,b2);
        }
        __syncthreads();
    }
    float acc[8][6];
#pragma unroll
    for (int i = 0; i < 8; i++) {
        UPK2(acc[i][0], acc[i][1], acc2[i][0]);
        UPK2(acc[i][2], acc[i][3], acc2[i][1]);
        UPK2(acc[i][4], acc[i][5], acc2[i][2]);
    }
    int o = o0 + tx*6;
    if (which == 1) {
#pragma unroll
        for (int i = 0; i < 8; i++) {
            int row = p0 + ty*8 + i;
#pragma unroll
            for (int c = 0; c < 6; c++) {
                int oo = o + c;
                g_KTd[(((size_t)n*NH + (oo >> 5))*DH + (oo & 31))*KPP + row] = acc[i][c];
            }
        }
    } else {
        float* out = (which == 0) ? (g_Q + (size_t)n*HP*CH) : (g_V + (size_t)n*KPP*CH);
#pragma unroll
        for (int i = 0; i < 8; i++) {
            float* base = out + (size_t)(p0 + ty*8 + i)*CH + o;
            *(float2*)(base    ) = make_float2(acc[i][0], acc[i][1]);
            *(float2*)(base + 2) = make_float2(acc[i][2], acc[i][3]);
            *(float2*)(base + 4) = make_float2(acc[i][4], acc[i][5]);
        }
    }
}

// =================================================================================
// Kernel 2: positional factor tables, layout [m][a][d][kk].
// =================================================================================
__global__ void pf_kernel(const float* __restrict__ Wx, const float* __restrict__ Wy)
{
    int a = blockIdx.x >> 5;
    int b = blockIdx.x & 31;
    const float* W = blockIdx.y ? Wy : Wx;
    float* out = blockIdx.y ? g_PFY : g_PFX;

    __shared__ float emb[144];
    int t = threadIdx.x;
    float diff = (float)a - 2.0f*(float)b;
    if (t < 72) {
        float dm  = powf(1000.0f, (4.0f/288.0f)*(float)t);
        float arg = diff / dm;
        emb[t]      = sinf(arg);
        emb[72 + t] = cosf(arg);
    }
    __syncthreads();
    const float inv_sqrt2 = 0.7071067811865476f;
    for (int j = t; j < CH; j += 144) {
        float s = 0.f;
        const float* wr = W + (size_t)j*144;
#pragma unroll 8
        for (int f = 0; f < 144; f++) s += emb[f]*wr[f];
        int m = j >> 5, dd = j & 31;
        out[(((size_t)m*64 + a)*32 + dd)*32 + b] = s * inv_sqrt2;
    }
}

// =================================================================================
// Kernel 3: bias tables EX/EY (64x32x32 GEMM per block) + ctx partial sums.
// =================================================================================
__global__ __launch_bounds__(256) void bias_kernel()
{
    int t = threadIdx.x;
    if (blockIdx.y == NH) {
        if (blockIdx.z >= 2 || blockIdx.x >= 32) return;
        int n = blockIdx.z, b = blockIdx.x;
        for (int c = t; c < CH; c += 256) {
            const float* q = g_Q + ((size_t)n*HP + b*128)*CH + c;
            float s = 0.f;
#pragma unroll 8
            for (int p = 0; p < 128; p++) s += q[(size_t)p*CH];
            g_ctxp[((size_t)n*32 + b)*CH + c] = s;
        }
        return;
    }

    int a   = blockIdx.x;
    int m   = blockIdx.y;
    int n   = blockIdx.z >> 1;
    int isX = blockIdx.z & 1;

    __shared__ float Qs2[32][68];   // [d][row]
    __shared__ float Ps[32*32];     // [d][kk]

    {
        const float* pf = (isX ? g_PFX : g_PFY) + ((size_t)(m*64 + a)*32)*32;
        ((float4*)Ps)[t] = ((const float4*)pf)[t];
    }
    {
        int r = t >> 2, jg = (t & 3) * 8;
        int q = isX ? (r*64 + a) : (a*64 + r);
        const float* qp = g_Q + ((size_t)n*HP + q)*CH + m*DH + jg;
        float4 v0 = *(const float4*)qp;
        float4 v1 = *(const float4*)(qp + 4);
        Qs2[jg+0][r] = v0.x; Qs2[jg+1][r] = v0.y; Qs2[jg+2][r] = v0.z; Qs2[jg+3][r] = v0.w;
        Qs2[jg+4][r] = v1.x; Qs2[jg+5][r] = v1.y; Qs2[jg+6][r] = v1.z; Qs2[jg+7][r] = v1.w;
    }
    __syncthreads();

    int row = t & 63, gk = t >> 6;
    float acc[8] = {};
#pragma unroll
    for (int d = 0; d < 32; d++) {
        float qv = Qs2[d][row];
        float4 pA = *(const float4*)&Ps[d*32 + gk*8];
        float4 pB = *(const float4*)&Ps[d*32 + gk*8 + 4];
        acc[0] += qv*pA.x; acc[1] += qv*pA.y; acc[2] += qv*pA.z; acc[3] += qv*pA.w;
        acc[4] += qv*pB.x; acc[5] += qv*pB.y; acc[6] += qv*pB.z; acc[7] += qv*pB.w;
    }
    int q = isX ? (row*64 + a) : (a*64 + row);
    float* outp = (isX ? g_EX : g_EY) + (((size_t)n*NH + m)*HP + q)*32 + gk*8;
    *(float4*)outp       = make_float4(acc[0], acc[1], acc[2], acc[3]);
    *(float4*)(outp + 4) = make_float4(acc[4], acc[5], acc[6], acc[7]);
}

// =================================================================================
// Kernel 4: attention.
// =================================================================================
#define AE_QS  0
#define AE_K0  4608
#define AE_K1  (AE_K0 + 16*1024)
#define AE_EX  (AE_K1 + 16*1024)
#define AE_EY  (AE_EX + 512)
#define AE_RD  (AE_EY + 512)
#define AE_CS  (AE_RD + 128)
#define AE_MX  (AE_CS + 288)
#define AE_TOT (AE_MX + 16)          // 38832 floats = 155,328 B

__device__ __forceinline__ void stage_half(float* buf, const float* kb, int t)
{
    unsigned int dst = (unsigned int)__cvta_generic_to_shared(buf);
#pragma unroll
    for (int i = 0; i < 16; i++) {
        int idx = t + i*256;
        int row = idx >> 8, c4 = (idx & 255)*4;
        CP_ASYNC16(dst + (unsigned int)(row*1024 + c4)*4u, kb + (size_t)row*KPP + c4);
    }
    CP_COMMIT();
}

__global__ __launch_bounds__(256, 1) void attn_e_kernel(
    const float* __restrict__ Wc, const float* __restrict__ bc)
{
    extern __shared__ float sm[];
    float* Qs   = sm + AE_QS;
    float* K0   = sm + AE_K0;
    float* K1   = sm + AE_K1;
    float* exs  = sm + AE_EX;
    float* eys  = sm + AE_EY;
    float* red  = sm + AE_RD;
    float* cs   = sm + AE_CS;
    float* mixs = sm + AE_MX;

    int n  = blockIdx.y;
    int q0 = blockIdx.x * TQ;
    int t  = threadIdx.x;
    int warp = t >> 5, lane = t & 31;

    const float* khead = g_KTd + ((size_t)n*NH)*DH*KPP;

    stage_half(K0, khead, t);
    stage_half(K1, khead + 16*KPP, t);

    for (int c = t; c < CH; c += 256) {
        float s = 0.f;
#pragma unroll
        for (int b = 0; b < 32; b++) s += g_ctxp[((size_t)n*32 + b)*CH + c];
        cs[c] = s * (1.0f/HP);
    }

    {
        const float4* src = (const float4*)(g_Q + ((size_t)n*HP + q0)*CH);
        float4* dst = (float4*)Qs;
#pragma unroll
        for (int i = 0; i < 5; i++) {
            int idx = t + i*256;
            if (idx < 1152) dst[idx] = src[idx];
        }
    }
    __syncthreads();
    if (t < NH) {
        float l = bc[t];
        const float* wr = Wc + (size_t)t*CH;
#pragma unroll 8
        for (int o = 0; o < CH; o++) l += cs[o]*wr[o];
        mixs[t] = l;
    }
    __syncthreads();
    if (t == 0) {
        float mx = mixs[0];
        for (int j = 1; j < NH; j++) mx = fmaxf(mx, mixs[j]);
        float sum = 0.f;
        for (int j = 0; j < NH; j++) { float e2 = expf(mixs[j]-mx); mixs[j] = e2; sum += e2; }
        float inv = 1.0f/sum;
        for (int j = 0; j < NH; j++) mixs[j] *= inv;
    }

    const int kt   = t & 127;
    const int kqA  = kt * 4;
    const int grp  = t >> 7;
    const int qb   = grp * 8;
    const int wgrp = warp & 3;

    const int wkA = kqA & 31;
    const int hkA = kqA >> 5;

    float ab[8][8] = {};

    for (int m = 0; m < NH; m++) {
        CP_WAIT(1);
        __syncthreads();   // (1)

        float mw = mixs[m];

        // ---- bias rows: one coalesced float4 per thread ----
        {
            const float4* ex = (const float4*)(g_EX + (((size_t)n*NH + m)*HP + q0)*32);
            const float4* ey = (const float4*)(g_EY + (((size_t)n*NH + m)*HP + q0)*32);
            if (t < 128) ((float4*)exs)[t]       = ex[t];
            else         ((float4*)eys)[t - 128] = ey[t - 128];
        }

        ull acc2[8][4] = {};

        // ---- QK half A (d = 0..15) ----
#pragma unroll
        for (int d4 = 0; d4 < 4; d4++) {
            const float* kbase = K0 + (d4*4)*1024;
            ulonglong2 kA0 = *(const ulonglong2*)(kbase          + kqA);
            ulonglong2 kA1 = *(const ulonglong2*)(kbase + 1024   + kqA);
            ulonglong2 kA2 = *(const ulonglong2*)(kbase + 2048   + kqA);
            ulonglong2 kA3 = *(const ulonglong2*)(kbase + 3072   + kqA);
            ulonglong2 kB0 = *(const ulonglong2*)(kbase + 512    + kqA);
            ulonglong2 kB1 = *(const ulonglong2*)(kbase + 1536   + kqA);
            ulonglong2 kB2 = *(const ulonglong2*)(kbase + 2560   + kqA);
            ulonglong2 kB3 = *(const ulonglong2*)(kbase + 3584   + kqA);
#pragma unroll
            for (int u = 0; u < 8; u++) {
                float4 qq = *(const float4*)&Qs[(qb+u)*CH + m*DH + d4*4];
                ull pa;
                PK2(pa, qq.x, qq.x);
                FMA2(acc2[u][0], pa, kA0.x); FMA2(acc2[u][1], pa, kA0.y);
                FMA2(acc2[u][2], pa, kB0.x); FMA2(acc2[u][3], pa, kB0.y);
                PK2(pa, qq.y, qq.y);
                FMA2(acc2[u][0], pa, kA1.x); FMA2(acc2[u][1], pa, kA1.y);
                FMA2(acc2[u][2], pa, kB1.x); FMA2(acc2[u][3], pa, kB1.y);
                PK2(pa, qq.z, qq.z);
                FMA2(acc2[u][0], pa, kA2.x); FMA2(acc2[u][1], pa, kA2.y);
                FMA2(acc2[u][2], pa, kB2.x); FMA2(acc2[u][3], pa, kB2.y);
                PK2(pa, qq.w, qq.w);
                FMA2(acc2[u][0], pa, kA3.x); FMA2(acc2[u][1], pa, kA3.y);
                FMA2(acc2[u][2], pa, kB3.x); FMA2(acc2[u][3], pa, kB3.y);
            }
        }
        __syncthreads();   // (2) done reading K0
        if (m < NH-1) stage_half(K0, khead + (size_t)(m+1)*DH*KPP, t);

        if (m < NH-1) { CP_WAIT(1); } else { CP_WAIT(0); }
        __syncthreads();   // (3) K1 ready

        // ---- QK half B (d = 16..31) ----
#pragma unroll
        for (int d4 = 0; d4 < 4; d4++) {
            const float* kbase = K1 + (d4*4)*1024;
            ulonglong2 kA0 = *(const ulonglong2*)(kbase          + kqA);
            ulonglong2 kA1 = *(const ulonglong2*)(kbase + 1024   + kqA);
            ulonglong2 kA2 = *(const ulonglong2*)(kbase + 2048   + kqA);
            ulonglong2 kA3 = *(const ulonglong2*)(kbase + 3072   + kqA);
            ulonglong2 kB0 = *(const ulonglong2*)(kbase + 512    + kqA);
            ulonglong2 kB1 = *(const ulonglong2*)(kbase + 1536   + kqA);
            ulonglong2 kB2 = *(const ulonglong2*)(kbase + 2560   + kqA);
            ulonglong2 kB3 = *(const ulonglong2*)(kbase + 3584   + kqA);
#pragma unroll
            for (int u = 0; u < 8; u++) {
                float4 qq = *(const float4*)&Qs[(qb+u)*CH + m*DH + 16 + d4*4];
                ull pa;
                PK2(pa, qq.x, qq.x);
                FMA2(acc2[u][0], pa, kA0.x); FMA2(acc2[u][1], pa, kA0.y);
                FMA2(acc2[u][2], pa, kB0.x); FMA2(acc2[u][3], pa, kB0.y);
                PK2(pa, qq.y, qq.y);
                FMA2(acc2[u][0], pa, kA1.x); FMA2(acc2[u][1], pa, kA1.y);
                FMA2(acc2[u][2], pa, kB1.x); FMA2(acc2[u][3], pa, kB1.y);
                PK2(pa, qq.z, qq.z);
                FMA2(acc2[u][0], pa, kA2.x); FMA2(acc2[u][1], pa, kA2.y);
                FMA2(acc2[u][2], pa, kB2.x); FMA2(acc2[u][3], pa, kB2.y);
                PK2(pa, qq.w, qq.w);
                FMA2(acc2[u][0], pa, kA3.x); FMA2(acc2[u][1], pa, kA3.y);
                FMA2(acc2[u][2], pa, kB3.x); FMA2(acc2[u][3], pa, kB3.y);
            }
        }
        __syncthreads();   // (4) done reading K1; exs/eys visible
        if (m < NH-1) stage_half(K1, khead + ((size_t)(m+1)*DH + 16)*KPP, t);

        // ---- bias add ----
        float e[8][8];
#pragma unroll
        for (int u = 0; u < 8; u++) {
            int qi = qb + u;
            float4 ex4 = *(const float4*)&exs[qi*32 + wkA];
            float eyA  = eys[qi*32 + hkA];
            float eyB  = eys[qi*32 + hkA + 16];
            float a0,a1,a2,a3;
            UPK2(a0,a1,acc2[u][0]); UPK2(a2,a3,acc2[u][1]);
            e[u][0] = a0 + ex4.x + eyA;
            e[u][1] = a1 + ex4.y + eyA;
            e[u][2] = a2 + ex4.z + eyA;
            e[u][3] = a3 + ex4.w + eyA;
            UPK2(a0,a1,acc2[u][2]); UPK2(a2,a3,acc2[u][3]);
            e[u][4] = a0 + ex4.x + eyB;
            e[u][5] = a1 + ex4.y + eyB;
            e[u][6] = a2 + ex4.z + eyB;
            e[u][7] = a3 + ex4.w + eyB;
        }

        // ---- softmax ----
        float mx[8];
#pragma unroll
        for (int u = 0; u < 8; u++) {
            float v = e[u][0];
#pragma unroll
            for (int j = 1; j < 8; j++) v = fmaxf(v, e[u][j]);
#pragma unroll
            for (int s2 = 16; s2; s2 >>= 1) v = fmaxf(v, __shfl_xor_sync(0xffffffffu, v, s2));
            mx[u] = v;
        }
        if (lane == 0) {
#pragma unroll
            for (int u = 0; u < 8; u++) red[grp*32 + wgrp*8 + u] = mx[u];
        }
        __syncthreads();   // (5)
#pragma unroll
        for (int u = 0; u < 8; u++) {
            float v = red[grp*32 + u];
            v = fmaxf(v, red[grp*32 + 8  + u]);
            v = fmaxf(v, red[grp*32 + 16 + u]);
            v = fmaxf(v, red[grp*32 + 24 + u]);
            mx[u] = v;
        }
        float sme[8];
#pragma unroll
        for (int u = 0; u < 8; u++) {
            float s = 0.f;
#pragma unroll
            for (int j = 0; j < 8; j++) {
                float p = __expf(e[u][j] - mx[u]);
                e[u][j] = p;
                s += p;
            }
#pragma unroll
            for (int s2 = 16; s2; s2 >>= 1) s += __shfl_xor_sync(0xffffffffu, s, s2);
            sme[u] = s;
        }
        if (lane == 0) {
#pragma unroll
            for (int u = 0; u < 8; u++) red[64 + grp*32 + wgrp*8 + u] = sme[u];
        }
        __syncthreads();   // (6)
#pragma unroll
        for (int u = 0; u < 8; u++) {
            float s = red[64 + grp*32 + u] + red[64 + grp*32 + 8 + u]
                    + red[64 + grp*32 + 16 + u] + red[64 + grp*32 + 24 + u];
            float sc = mw / s;
#pragma unroll
            for (int j = 0; j < 8; j++) ab[u][j] += e[u][j] * sc;
        }
    }

#pragma unroll
    for (int u = 0; u < 8; u++) {
        float* arow = g_Atn + ((size_t)n*HP + q0 + qb + u)*KPP;
        *(float4*)&arow[kqA]       = make_float4(ab[u][0], ab[u][1], ab[u][2], ab[u][3]);
        *(float4*)&arow[512 + kqA] = make_float4(ab[u][4], ab[u][5], ab[u][6], ab[u][7]);
    }
}

// =================================================================================
// Kernel 5: PV GEMM.  BM=64, BN=96, BK=16, 128 threads, 8x6 per thread.
// =================================================================================
__global__ __launch_bounds__(128) void pv_kernel()
{
    int n    = blockIdx.z;
    int row0 = blockIdx.x * 64;
    int o0   = blockIdx.y * 96;

    __shared__ float As[16][68];
    __shared__ float Bs[16][96];

    int t  = threadIdx.x;
    int tx = t & 15, ty = t >> 4;

    const float* A = g_Atn + ((size_t)n*HP + row0)*KPP;
    const float* V = g_V + (size_t)n*KPP*CH + o0;

    ull acc2[8][3] = {};

    for (int k0 = 0; k0 < KPP; k0 += 16) {
#pragma unroll
        for (int i = 0; i < 8; i++) {
            int e = t + i*128;
            int row = e >> 4, k = e & 15;
            As[k][row] = A[(size_t)row*KPP + k0 + k];
        }
#pragma unroll
        for (int i = 0; i < 12; i++) {
            int e = t + i*128;
            int k = e / 96, col = e % 96;
            Bs[k][col] = V[(size_t)(k0 + k)*CH + col];
        }
        __syncthreads();
#pragma unroll
        for (int k = 0; k < 16; k++) {
            float4 a0 = *(const float4*)&As[k][ty*8];
            float4 a1 = *(const float4*)&As[k][ty*8 + 4];
            ull b0 = *(const ull*)&Bs[k][tx*6];
            ull b1 = *(const ull*)&Bs[k][tx*6 + 2];
            ull b2 = *(const ull*)&Bs[k][tx*6 + 4];
            ull pa;
            PK2(pa, a0.x, a0.x); FMA2(acc2[0][0],pa,b0); FMA2(acc2[0][1],pa,b1); FMA2(acc2[0][2],pa,b2);
            PK2(pa, a0.y, a0.y); FMA2(acc2[1][0],pa,b0); FMA2(acc2[1][1],pa,b1); FMA2(acc2[1][2],pa,b2);
            PK2(pa, a0.z, a0.z); FMA2(acc2[2][0],pa,b0); FMA2(acc2[2][1],pa,b1); FMA2(acc2[2][2],pa,b2);
            PK2(pa, a0.w, a0.w); FMA2(acc2[3][0],pa,b0); FMA2(acc2[3][1],pa,b1); FMA2(acc2[3][2],pa,b2);
            PK2(pa, a1.x, a1.x); FMA2(acc2[4][0],pa,b0); FMA2(acc2[4][1],pa,b1); FMA2(acc2[4][2],pa,b2);
            PK2(pa, a1.y, a1.y); FMA2(acc2[5][0],pa,b0); FMA2(acc2[5][1],pa,b1); FMA2(acc2[5][2],pa,b2);
            PK2(pa, a1.z, a1.z); FMA2(acc2[6][0],pa,b0); FMA2(acc2[6][1],pa,b1); FMA2(acc2[6][2],pa,b2);
            PK2(pa, a1.w, a1.w); FMA2(acc2[7][0],pa,b0); FMA2(acc2[7][1],pa,b1); FMA2(acc2[7][2],pa,b2);
        }
        __syncthreads();
    }

    float* O = g_O + ((size_t)n*HP + row0)*CH + o0;
#pragma unroll
    for (int i = 0; i < 8; i++) {
        float v0,v1,v2,v3,v4,v5;
        UPK2(v0,v1,acc2[i][0]);
        UPK2(v2,v3,acc2[i][1]);
        UPK2(v4,v5,acc2[i][2]);
        float* orow = O + (size_t)(ty*8 + i)*CH + tx*6;
        *(float2*)&orow[0] = make_float2(v0,v1);
        *(float2*)&orow[2] = make_float2(v2,v3);
        *(float2*)&orow[4] = make_float2(v4,v5);
    }
}

// =================================================================================
// Kernel 6: final projection + residual.  BM=128 pix x BN=96 o, 6x8 per thread.
// =================================================================================
__global__ __launch_bounds__(256) void proj_kernel(
    const float* __restrict__ x,
    const float* __restrict__ Wp,
    const float* __restrict__ bp,
    const float* __restrict__ gamma,
    float* __restrict__ out)
{
    int n  = blockIdx.z;
    int p0 = blockIdx.x * 128;
    int o0 = blockIdx.y * 96;
    const float* A = g_O + (size_t)n*HP*CH;

    __shared__ float As[32][132];
    __shared__ float Bs[32][96];

    int t  = threadIdx.x;
    int tx = t & 15, ty = t >> 4;
    ull acc2[6][4] = {};   // [o][pix-pair]

    for (int c0 = 0; c0 < CH; c0 += 32) {
#pragma unroll
        for (int i = 0; i < 16; i++) {
            int idx = t + i*256;
            int pix = idx >> 5, c = idx & 31;
            As[c][pix] = A[(size_t)(p0 + pix)*CH + c0 + c];
        }
#pragma unroll
        for (int i = 0; i < 12; i++) {
            int idx = t + i*256;
            int o = idx >> 5, c = idx & 31;
            Bs[c][o] = Wp[(size_t)(o0 + o)*CH + c0 + c];
        }
        __syncthreads();
#pragma unroll
        for (int c = 0; c < 32; c++) {
            ulonglong2 a01 = *(const ulonglong2*)&As[c][ty*8];
            ulonglong2 a23 = *(const ulonglong2*)&As[c][ty*8 + 4];
            float2 bA = *(const float2*)&Bs[c][tx*6];
            float2 bB = *(const float2*)&Bs[c][tx*6 + 2];
            float2 bC = *(const float2*)&Bs[c][tx*6 + 4];
            ull pb;
            PK2(pb, bA.x, bA.x); FMA2(acc2[0][0],pb,a01.x); FMA2(acc2[0][1],pb,a01.y); FMA2(acc2[0][2],pb,a23.x); FMA2(acc2[0][3],pb,a23.y);
            PK2(pb, bA.y, bA.y); FMA2(acc2[1][0],pb,a01.x); FMA2(acc2[1][1],pb,a01.y); FMA2(acc2[1][2],pb,a23.x); FMA2(acc2[1][3],pb,a23.y);
            PK2(pb, bB.x, bB.x); FMA2(acc2[2][0],pb,a01.x); FMA2(acc2[2][1],pb,a01.y); FMA2(acc2[2][2],pb,a23.x); FMA2(acc2[2][3],pb,a23.y);
            PK2(pb, bB.y, bB.y); FMA2(acc2[3][0],pb,a01.x); FMA2(acc2[3][1],pb,a01.y); FMA2(acc2[3][2],pb,a23.x); FMA2(acc2[3][3],pb,a23.y);
            PK2(pb, bC.x, bC.x); FMA2(acc2[4][0],pb,a01.x); FMA2(acc2[4][1],pb,a01.y); FMA2(acc2[4][2],pb,a23.x); FMA2(acc2[4][3],pb,a23.y);
            PK2(pb, bC.y, bC.y); FMA2(acc2[5][0],pb,a01.x); FMA2(acc2[5][1],pb,a01.y); FMA2(acc2[5][2],pb,a23.x); FMA2(acc2[5][3],pb,a23.y);
        }
        __syncthreads();
    }
    float g = gamma[0];
    int p = p0 + ty*8;
#pragma unroll
    for (int j = 0; j < 6; j++) {
        int o = o0 + tx*6 + j;
        float v0,v1,v2,v3,v4,v5,v6,v7;
        UPK2(v0,v1,acc2[j][0]); UPK2(v2,v3,acc2[j][1]);
        UPK2(v4,v5,acc2[j][2]); UPK2(v6,v7,acc2[j][3]);
        float bb = bp[o];
        size_t base = (size_t)n*CH*HP + (size_t)o*HP + p;
        float4 x0 = *(const float4*)(x + base);
        float4 x1 = *(const float4*)(x + base + 4);
        float4 r0, r1;
        r0.x = g*(v0+bb) + x0.x; r0.y = g*(v1+bb) + x0.y;
        r0.z = g*(v2+bb) + x0.z; r0.w = g*(v3+bb) + x0.w;
        r1.x = g*(v4+bb) + x1.x; r1.y = g*(v5+bb) + x1.y;
        r1.z = g*(v6+bb) + x1.z; r1.w = g*(v7+bb) + x1.w;
        *(float4*)(out + base)     = r0;
        *(float4*)(out + base + 4) = r1;
    }
}

// =================================================================================
extern "C" void kernel_launch(void* const* d_in, const int* in_sizes, int n_in,
                              void* d_out, int out_size)
{
    const float* x     = (const float*)d_in[0];
    const float* Wq    = (const float*)d_in[1];
    const float* Wk    = (const float*)d_in[2];
    const float* Wv    = (const float*)d_in[3];
    const float* Wx    = (const float*)d_in[4];
    const float* Wy    = (const float*)d_in[5];
    const float* Wproj = (const float*)d_in[6];
    const float* bproj = (const float*)d_in[7];
    const float* Wc    = (const float*)d_in[8];
    const float* bc    = (const float*)d_in[9];
    const float* gamma = (const float*)d_in[10];
    float* out = (float*)d_out;

    cudaFuncSetAttribute(attn_e_kernel, cudaFuncAttributeMaxDynamicSharedMemorySize,
                         AE_TOT * (int)sizeof(float));

    pf_kernel<<<dim3(2048, 2), 144>>>(Wx, Wy);                 // 1
    qkv_kernel<<<dim3(32, 3, 6), 256>>>(x, Wq, Wk, Wv);        // 2
    bias_kernel<<<dim3(64, NH + 1, 4), 256>>>();               // 3 (bias + ctx)
    attn_e_kernel<<<dim3(HP/TQ, NB), 256,                      // 4  <- ncu window
                    AE_TOT * (int)sizeof(float)>>>(Wc, bc);
    pv_kernel<<<dim3(HP/64, 3, NB), 128>>>();                  // 5
    proj_kernel<<<dim3(32, 3, 2), 256>>>(x, Wproj, bproj, gamma, out);  // 6
}

// round 14
// speedup vs baseline: 1.0100x; 1.0100x over previous
#include <cuda_runtime.h>
#include <math.h>

#define NB  2
#define CH  288
#define HP  4096
#define KPP 1024
#define NH  9
#define DH  32
#define TQ  16

typedef unsigned long long ull;

// ---- packed f32x2 FMA (sm_103a FFMA2; PTX-only path) ----
#define FMA2(d, a, b) asm("fma.rn.f32x2 %0, %1, %2, %0;" : "+l"(d) : "l"(a), "l"(b))
#define PK2(d, lo, hi) asm("mov.b64 %0, {%1, %2};" : "=l"(d) : "r"(__float_as_uint(lo)), "r"(__float_as_uint(hi)))
#define UPK2(lo, hi, v) do { unsigned int _ul, _uh; \
    asm("mov.b64 {%0, %1}, %2;" : "=r"(_ul), "=r"(_uh) : "l"(v)); \
    (lo) = __uint_as_float(_ul); (hi) = __uint_as_float(_uh); } while (0)

// ---- cp.async helpers ----
#define CP_ASYNC16(dst_u32, src_ptr) \
    asm volatile("cp.async.cg.shared.global [%0], [%1], 16;" :: "r"(dst_u32), "l"(src_ptr))
#define CP_COMMIT() asm volatile("cp.async.commit_group;")
#define CP_WAIT(n)  asm volatile("cp.async.wait_group %0;" :: "n"(n))

// ---------------- device scratch ----------------
__device__ float g_Q   [NB*HP*CH];
__device__ float g_KTd [NB*NH*DH*KPP];   // k[n][m][dd][kp]
__device__ float g_V   [NB*KPP*CH];
__device__ float g_O   [NB*HP*CH];
__device__ float g_PFX [NH*64*32*DH];    // pfx[m][a][d][kk]
__device__ float g_PFY [NH*64*32*DH];    // pfy[m][a][d][kk]
__device__ float g_EX  [NB*NH*HP*32];    // ex[n][m][q][wk]
__device__ float g_EY  [NB*NH*HP*32];    // ey[n][m][q][hk]
__device__ float g_Atn [NB*HP*KPP];
__device__ float g_ctxp[NB*32*CH];

// =================================================================================
// Kernel 1: Q/K/V projections.  R9-measured 64x64/4x4 tile.
// =================================================================================
__global__ __launch_bounds__(256) void qkv_kernel(
    const float* __restrict__ x,
    const float* __restrict__ Wq,
    const float* __restrict__ Wk,
    const float* __restrict__ Wv)
{
    int which = blockIdx.z >> 1;
    int n     = blockIdx.z & 1;
    int rows  = (which == 0) ? HP : KPP;
    int p0    = blockIdx.x * 64;
    if (p0 >= rows) return;
    int o0    = blockIdx.y * 64;

    const float* W = (which == 0) ? Wq : (which == 1 ? Wk : Wv);
    const float* xb = x + (size_t)n*CH*HP;

    __shared__ float As[32][64];
    __shared__ float Bs[32][68];

    int t  = threadIdx.x;
    int tx = t & 15, ty = t >> 4;
    ull acc2[4][2] = {};

    for (int c0 = 0; c0 < CH; c0 += 32) {
#pragma unroll
        for (int i = 0; i < 8; i++) {
            int idx = t + i*256;
            int c = idx >> 6, pix = idx & 63;
            int row = p0 + pix;
            int pixel = (which == 0) ? row : (((row >> 5) << 7) | ((row & 31) << 1));
            As[c][pix] = xb[(size_t)(c0 + c)*HP + pixel];
        }
#pragma unroll
        for (int i = 0; i < 8; i++) {
            int idx = t + i*256;
            int o = idx >> 5, c = idx & 31;
            int oo = o0 + o;
            Bs[c][o] = (oo < CH) ? W[(size_t)oo*CH + c0 + c] : 0.f;
        }
        __syncthreads();
#pragma unroll
        for (int c = 0; c < 32; c++) {
            float4 a = *(const float4*)&As[c][ty*4];
            ulonglong2 b2 = *(const ulonglong2*)&Bs[c][tx*4];
            ull pa;
            PK2(pa, a.x, a.x); FMA2(acc2[0][0], pa, b2.x); FMA2(acc2[0][1], pa, b2.y);
            PK2(pa, a.y, a.y); FMA2(acc2[1][0], pa, b2.x); FMA2(acc2[1][1], pa, b2.y);
            PK2(pa, a.z, a.z); FMA2(acc2[2][0], pa, b2.x); FMA2(acc2[2][1], pa, b2.y);
            PK2(pa, a.w, a.w); FMA2(acc2[3][0], pa, b2.x); FMA2(acc2[3][1], pa, b2.y);
        }
        __syncthreads();
    }
    float acc[4][4];
#pragma unroll
    for (int i = 0; i < 4; i++) {
        UPK2(acc[i][0], acc[i][1], acc2[i][0]);
        UPK2(acc[i][2], acc[i][3], acc2[i][1]);
    }
    int o = o0 + tx*4;
    if (o >= CH) return;

    if (which == 1) {
#pragma unroll
        for (int i = 0; i < 4; i++) {
            int row = p0 + ty*4 + i;
#pragma unroll
            for (int c = 0; c < 4; c++) {
                int oo = o + c;
                g_KTd[(((size_t)n*NH + (oo >> 5))*DH + (oo & 31))*KPP + row] = acc[i][c];
            }
        }
    } else {
        float* out = (which == 0) ? (g_Q + (size_t)n*HP*CH) : (g_V + (size_t)n*KPP*CH);
#pragma unroll
        for (int i = 0; i < 4; i++) {
            int row = p0 + ty*4 + i;
            *(float4*)&out[(size_t)row*CH + o] =
                make_float4(acc[i][0], acc[i][1], acc[i][2], acc[i][3]);
        }
    }
}

// =================================================================================
// Kernel 2: positional factor tables, layout [m][a][d][kk].
// =================================================================================
__global__ void pf_kernel(const float* __restrict__ Wx, const float* __restrict__ Wy)
{
    int a = blockIdx.x >> 5;
    int b = blockIdx.x & 31;
    const float* W = blockIdx.y ? Wy : Wx;
    float* out = blockIdx.y ? g_PFY : g_PFX;

    __shared__ float emb[144];
    int t = threadIdx.x;
    float diff = (float)a - 2.0f*(float)b;
    if (t < 72) {
        float dm  = powf(1000.0f, (4.0f/288.0f)*(float)t);
        float arg = diff / dm;
        emb[t]      = sinf(arg);
        emb[72 + t] = cosf(arg);
    }
    __syncthreads();
    const float inv_sqrt2 = 0.7071067811865476f;
    for (int j = t; j < CH; j += 144) {
        float s = 0.f;
        const float* wr = W + (size_t)j*144;
#pragma unroll 8
        for (int f = 0; f < 144; f++) s += emb[f]*wr[f];
        int m = j >> 5, dd = j & 31;
        out[(((size_t)m*64 + a)*32 + dd)*32 + b] = s * inv_sqrt2;
    }
}

// =================================================================================
// Kernel 3: bias tables EX/EY + ctx partial sums.
// =================================================================================
__global__ __launch_bounds__(256) void bias_kernel()
{
    int t = threadIdx.x;
    if (blockIdx.y == NH) {
        if (blockIdx.z >= 2 || blockIdx.x >= 32) return;
        int n = blockIdx.z, b = blockIdx.x;
        for (int c = t; c < CH; c += 256) {
            const float* q = g_Q + ((size_t)n*HP + b*128)*CH + c;
            float s = 0.f;
#pragma unroll 8
            for (int p = 0; p < 128; p++) s += q[(size_t)p*CH];
            g_ctxp[((size_t)n*32 + b)*CH + c] = s;
        }
        return;
    }

    int a   = blockIdx.x;
    int m   = blockIdx.y;
    int n   = blockIdx.z >> 1;
    int isX = blockIdx.z & 1;

    __shared__ float Qs2[32][68];
    __shared__ float Ps[32*32];

    {
        const float* pf = (isX ? g_PFX : g_PFY) + ((size_t)(m*64 + a)*32)*32;
        ((float4*)Ps)[t] = ((const float4*)pf)[t];
    }
    {
        int r = t >> 2, jg = (t & 3) * 8;
        int q = isX ? (r*64 + a) : (a*64 + r);
        const float* qp = g_Q + ((size_t)n*HP + q)*CH + m*DH + jg;
        float4 v0 = *(const float4*)qp;
        float4 v1 = *(const float4*)(qp + 4);
        Qs2[jg+0][r] = v0.x; Qs2[jg+1][r] = v0.y; Qs2[jg+2][r] = v0.z; Qs2[jg+3][r] = v0.w;
        Qs2[jg+4][r] = v1.x; Qs2[jg+5][r] = v1.y; Qs2[jg+6][r] = v1.z; Qs2[jg+7][r] = v1.w;
    }
    __syncthreads();

    int row = t & 63, gk = t >> 6;
    float acc[8] = {};
#pragma unroll
    for (int d = 0; d < 32; d++) {
        float qv = Qs2[d][row];
        float4 pA = *(const float4*)&Ps[d*32 + gk*8];
        float4 pB = *(const float4*)&Ps[d*32 + gk*8 + 4];
        acc[0] += qv*pA.x; acc[1] += qv*pA.y; acc[2] += qv*pA.z; acc[3] += qv*pA.w;
        acc[4] += qv*pB.x; acc[5] += qv*pB.y; acc[6] += qv*pB.z; acc[7] += qv*pB.w;
    }
    int q = isX ? (row*64 + a) : (a*64 + row);
    float* outp = (isX ? g_EX : g_EY) + (((size_t)n*NH + m)*HP + q)*32 + gk*8;
    *(float4*)outp       = make_float4(acc[0], acc[1], acc[2], acc[3]);
    *(float4*)(outp + 4) = make_float4(acc[4], acc[5], acc[6], acc[7]);
}

// =================================================================================
// Kernel 4: attention.  512 threads (16 warps), 8q x 4k per thread,
// cp.async double-buffered K halves.
// =================================================================================
#define AE_QS  0
#define AE_K0  4608
#define AE_K1  (AE_K0 + 16*1024)
#define AE_EX  (AE_K1 + 16*1024)
#define AE_EY  (AE_EX + 512)
#define AE_RD  (AE_EY + 512)
#define AE_CS  (AE_RD + 256)
#define AE_MX  (AE_CS + 288)
#define AE_TOT (AE_MX + 16)          // 38960 floats = 155,840 B

__device__ __forceinline__ void stage_half(float* buf, const float* kb, int t)
{
    unsigned int dst = (unsigned int)__cvta_generic_to_shared(buf);
#pragma unroll
    for (int i = 0; i < 8; i++) {
        int idx = t + i*512;
        int row = idx >> 8, c4 = (idx & 255)*4;
        CP_ASYNC16(dst + (unsigned int)(row*1024 + c4)*4u, kb + (size_t)row*KPP + c4);
    }
    CP_COMMIT();
}

__global__ __launch_bounds__(512, 1) void attn_e_kernel(
    const float* __restrict__ Wc, const float* __restrict__ bc)
{
    extern __shared__ float sm[];
    float* Qs   = sm + AE_QS;
    float* K0   = sm + AE_K0;
    float* K1   = sm + AE_K1;
    float* exs  = sm + AE_EX;
    float* eys  = sm + AE_EY;
    float* red  = sm + AE_RD;
    float* cs   = sm + AE_CS;
    float* mixs = sm + AE_MX;

    int n  = blockIdx.y;
    int q0 = blockIdx.x * TQ;
    int t  = threadIdx.x;
    int warp = t >> 5, lane = t & 31;

    const float* khead = g_KTd + ((size_t)n*NH)*DH*KPP;

    stage_half(K0, khead, t);
    stage_half(K1, khead + 16*KPP, t);

    if (t < CH) {
        float s = 0.f;
#pragma unroll
        for (int b = 0; b < 32; b++) s += g_ctxp[((size_t)n*32 + b)*CH + t];
        cs[t] = s * (1.0f/HP);
    }

    {
        const float4* src = (const float4*)(g_Q + ((size_t)n*HP + q0)*CH);
        float4* dst = (float4*)Qs;
#pragma unroll
        for (int i = 0; i < 3; i++) {
            int idx = t + i*512;
            if (idx < 1152) dst[idx] = src[idx];
        }
    }
    __syncthreads();
    if (t < NH) {
        float l = bc[t];
        const float* wr = Wc + (size_t)t*CH;
#pragma unroll 8
        for (int o = 0; o < CH; o++) l += cs[o]*wr[o];
        mixs[t] = l;
    }
    __syncthreads();
    if (t == 0) {
        float mx = mixs[0];
        for (int j = 1; j < NH; j++) mx = fmaxf(mx, mixs[j]);
        float sum = 0.f;
        for (int j = 0; j < NH; j++) { float e2 = expf(mixs[j]-mx); mixs[j] = e2; sum += e2; }
        float inv = 1.0f/sum;
        for (int j = 0; j < NH; j++) mixs[j] *= inv;
    }

    const int kt   = t & 255;       // 256 key-threads
    const int kq   = kt * 2;        // keys kq,kq+1 (and 512+kq,512+kq+1)
    const int grp  = t >> 8;        // q-group 0/1 (8 queries each)
    const int qb   = grp * 8;
    const int wgrp = warp & 7;      // warp within q-group (8 warps)

    const int wk  = kq & 31;
    const int hkA = kq >> 5;        // 0..15; second half: 16 + hkA

    float ab[8][4] = {};

    for (int m = 0; m < NH; m++) {
        CP_WAIT(1);
        __syncthreads();   // (1)

        float mw = mixs[m];

        // ---- bias rows: coalesced table loads ----
        {
            const float4* ex = (const float4*)(g_EX + (((size_t)n*NH + m)*HP + q0)*32);
            const float4* ey = (const float4*)(g_EY + (((size_t)n*NH + m)*HP + q0)*32);
            if (t < 128)      ((float4*)exs)[t]       = ex[t];
            else if (t < 256) ((float4*)eys)[t - 128] = ey[t - 128];
        }

        ull acc2[8][2] = {};   // [q][key-half], 2 keys per ull

        // ---- QK phase A: d = 0..15 from K0 ----
#pragma unroll
        for (int d4 = 0; d4 < 4; d4++) {
            const float* kb0 = K0 + (d4*4)*1024;
            ull a0 = *(const ull*)(kb0          + kq);
            ull a1 = *(const ull*)(kb0 + 1024   + kq);
            ull a2 = *(const ull*)(kb0 + 2048   + kq);
            ull a3 = *(const ull*)(kb0 + 3072   + kq);
            ull b0 = *(const ull*)(kb0 + 512    + kq);
            ull b1 = *(const ull*)(kb0 + 1536   + kq);
            ull b2 = *(const ull*)(kb0 + 2560   + kq);
            ull b3 = *(const ull*)(kb0 + 3584   + kq);
#pragma unroll
            for (int u = 0; u < 8; u++) {
                float4 qq = *(const float4*)&Qs[(qb+u)*CH + m*DH + d4*4];
                ull pa;
                PK2(pa, qq.x, qq.x); FMA2(acc2[u][0], pa, a0); FMA2(acc2[u][1], pa, b0);
                PK2(pa, qq.y, qq.y); FMA2(acc2[u][0], pa, a1); FMA2(acc2[u][1], pa, b1);
                PK2(pa, qq.z, qq.z); FMA2(acc2[u][0], pa, a2); FMA2(acc2[u][1], pa, b2);
                PK2(pa, qq.w, qq.w); FMA2(acc2[u][0], pa, a3); FMA2(acc2[u][1], pa, b3);
            }
        }
        __syncthreads();   // (2) done reading K0
        if (m < NH-1) stage_half(K0, khead + (size_t)(m+1)*DH*KPP, t);

        if (m < NH-1) { CP_WAIT(1); } else { CP_WAIT(0); }
        __syncthreads();   // (3) K1 ready

        // ---- QK phase B: d = 16..31 from K1 ----
#pragma unroll
        for (int d4 = 0; d4 < 4; d4++) {
            const float* kb1 = K1 + (d4*4)*1024;
            ull a0 = *(const ull*)(kb1          + kq);
            ull a1 = *(const ull*)(kb1 + 1024   + kq);
            ull a2 = *(const ull*)(kb1 + 2048   + kq);
            ull a3 = *(const ull*)(kb1 + 3072   + kq);
            ull b0 = *(const ull*)(kb1 + 512    + kq);
            ull b1 = *(const ull*)(kb1 + 1536   + kq);
            ull b2 = *(const ull*)(kb1 + 2560   + kq);
            ull b3 = *(const ull*)(kb1 + 3584   + kq);
#pragma unroll
            for (int u = 0; u < 8; u++) {
                float4 qq = *(const float4*)&Qs[(qb+u)*CH + m*DH + 16 + d4*4];
                ull pa;
                PK2(pa, qq.x, qq.x); FMA2(acc2[u][0], pa, a0); FMA2(acc2[u][1], pa, b0);
                PK2(pa, qq.y, qq.y); FMA2(acc2[u][0], pa, a1); FMA2(acc2[u][1], pa, b1);
                PK2(pa, qq.z, qq.z); FMA2(acc2[u][0], pa, a2); FMA2(acc2[u][1], pa, b2);
                PK2(pa, qq.w, qq.w); FMA2(acc2[u][0], pa, a3); FMA2(acc2[u][1], pa, b3);
            }
        }
        __syncthreads();   // (4) done reading K1; exs/eys visible
        if (m < NH-1) stage_half(K1, khead + ((size_t)(m+1)*DH + 16)*KPP, t);

        // ---- bias add (4 keys per thread) ----
        float e[8][4];
#pragma unroll
        for (int u = 0; u < 8; u++) {
            int qi = qb + u;
            float2 ex2 = *(const float2*)&exs[qi*32 + wk];
            float eyA  = eys[qi*32 + hkA];
            float eyB  = eys[qi*32 + 16 + hkA];
            float a0,a1;
            UPK2(a0,a1,acc2[u][0]);
            e[u][0] = a0 + ex2.x + eyA;
            e[u][1] = a1 + ex2.y + eyA;
            UPK2(a0,a1,acc2[u][1]);
            e[u][2] = a0 + ex2.x + eyB;
            e[u][3] = a1 + ex2.y + eyB;
        }

        // ---- softmax: 8 warps per q-group ----
        float mx[8];
#pragma unroll
        for (int u = 0; u < 8; u++) {
            float v = fmaxf(fmaxf(e[u][0], e[u][1]), fmaxf(e[u][2], e[u][3]));
#pragma unroll
            for (int s2 = 16; s2; s2 >>= 1) v = fmaxf(v, __shfl_xor_sync(0xffffffffu, v, s2));
            mx[u] = v;
        }
        if (lane == 0) {
#pragma unroll
            for (int u = 0; u < 8; u++) red[grp*64 + wgrp*8 + u] = mx[u];
        }
        __syncthreads();   // (5)
#pragma unroll
        for (int u = 0; u < 8; u++) {
            float v = red[grp*64 + u];
#pragma unroll
            for (int w = 1; w < 8; w++) v = fmaxf(v, red[grp*64 + w*8 + u]);
            mx[u] = v;
        }
        float sme[8];
#pragma unroll
        for (int u = 0; u < 8; u++) {
            float s = 0.f;
#pragma unroll
            for (int j = 0; j < 4; j++) {
                float p = __expf(e[u][j] - mx[u]);
                e[u][j] = p;
                s += p;
            }
#pragma unroll
            for (int s2 = 16; s2; s2 >>= 1) s += __shfl_xor_sync(0xffffffffu, s, s2);
            sme[u] = s;
        }
        if (lane == 0) {
#pragma unroll
            for (int u = 0; u < 8; u++) red[128 + grp*64 + wgrp*8 + u] = sme[u];
        }
        __syncthreads();   // (6)
#pragma unroll
        for (int u = 0; u < 8; u++) {
            float s = red[128 + grp*64 + u];
#pragma unroll
            for (int w = 1; w < 8; w++) s += red[128 + grp*64 + w*8 + u];
            float sc = mw / s;
#pragma unroll
            for (int j = 0; j < 4; j++) ab[u][j] += e[u][j] * sc;
        }
    }

    // ---- write combined attention ----
#pragma unroll
    for (int u = 0; u < 8; u++) {
        float* arow = g_Atn + ((size_t)n*HP + q0 + qb + u)*KPP;
        *(float2*)&arow[kq]       = make_float2(ab[u][0], ab[u][1]);
        *(float2*)&arow[512 + kq] = make_float2(ab[u][2], ab[u][3]);
    }
}

// =================================================================================
// Kernel 5: PV GEMM.  BM=64, BN=96, BK=16, 128 threads, 8x6 per thread.
// =================================================================================
__global__ __launch_bounds__(128) void pv_kernel()
{
    int n    = blockIdx.z;
    int row0 = blockIdx.x * 64;
    int o0   = blockIdx.y * 96;

    __shared__ float As[16][68];
    __shared__ float Bs[16][96];

    int t  = threadIdx.x;
    int tx = t & 15, ty = t >> 4;

    const float* A = g_Atn + ((size_t)n*HP + row0)*KPP;
    const float* V = g_V + (size_t)n*KPP*CH + o0;

    ull acc2[8][3] = {};

    for (int k0 = 0; k0 < KPP; k0 += 16) {
#pragma unroll
        for (int i = 0; i < 8; i++) {
            int e = t + i*128;
            int row = e >> 4, k = e & 15;
            As[k][row] = A[(size_t)row*KPP + k0 + k];
        }
#pragma unroll
        for (int i = 0; i < 12; i++) {
            int e = t + i*128;
            int k = e / 96, col = e % 96;
            Bs[k][col] = V[(size_t)(k0 + k)*CH + col];
        }
        __syncthreads();
#pragma unroll
        for (int k = 0; k < 16; k++) {
            float4 a0 = *(const float4*)&As[k][ty*8];
            float4 a1 = *(const float4*)&As[k][ty*8 + 4];
            ull b0 = *(const ull*)&Bs[k][tx*6];
            ull b1 = *(const ull*)&Bs[k][tx*6 + 2];
            ull b2 = *(const ull*)&Bs[k][tx*6 + 4];
            ull pa;
            PK2(pa, a0.x, a0.x); FMA2(acc2[0][0],pa,b0); FMA2(acc2[0][1],pa,b1); FMA2(acc2[0][2],pa,b2);
            PK2(pa, a0.y, a0.y); FMA2(acc2[1][0],pa,b0); FMA2(acc2[1][1],pa,b1); FMA2(acc2[1][2],pa,b2);
            PK2(pa, a0.z, a0.z); FMA2(acc2[2][0],pa,b0); FMA2(acc2[2][1],pa,b1); FMA2(acc2[2][2],pa,b2);
            PK2(pa, a0.w, a0.w); FMA2(acc2[3][0],pa,b0); FMA2(acc2[3][1],pa,b1); FMA2(acc2[3][2],pa,b2);
            PK2(pa, a1.x, a1.x); FMA2(acc2[4][0],pa,b0); FMA2(acc2[4][1],pa,b1); FMA2(acc2[4][2],pa,b2);
            PK2(pa, a1.y, a1.y); FMA2(acc2[5][0],pa,b0); FMA2(acc2[5][1],pa,b1); FMA2(acc2[5][2],pa,b2);
            PK2(pa, a1.z, a1.z); FMA2(acc2[6][0],pa,b0); FMA2(acc2[6][1],pa,b1); FMA2(acc2[6][2],pa,b2);
            PK2(pa, a1.w, a1.w); FMA2(acc2[7][0],pa,b0); FMA2(acc2[7][1],pa,b1); FMA2(acc2[7][2],pa,b2);
        }
        __syncthreads();
    }

    float* O = g_O + ((size_t)n*HP + row0)*CH + o0;
#pragma unroll
    for (int i = 0; i < 8; i++) {
        float v0,v1,v2,v3,v4,v5;
        UPK2(v0,v1,acc2[i][0]);
        UPK2(v2,v3,acc2[i][1]);
        UPK2(v4,v5,acc2[i][2]);
        float* orow = O + (size_t)(ty*8 + i)*CH + tx*6;
        *(float2*)&orow[0] = make_float2(v0,v1);
        *(float2*)&orow[2] = make_float2(v2,v3);
        *(float2*)&orow[4] = make_float2(v4,v5);
    }
}

// =================================================================================
// Kernel 6: final projection + residual.  R9 64x64/4x4 tile.
// =================================================================================
__global__ __launch_bounds__(256) void proj_kernel(
    const float* __restrict__ x,
    const float* __restrict__ Wp,
    const float* __restrict__ bp,
    const float* __restrict__ gamma,
    float* __restrict__ out)
{
    int n  = blockIdx.z;
    int p0 = blockIdx.x * 64;
    int o0 = blockIdx.y * 64;
    const float* A = g_O + (size_t)n*HP*CH;

    __shared__ float As[32][68];
    __shared__ float Bs[32][68];

    int t  = threadIdx.x;
    int tx = t & 15, ty = t >> 4;
    ull acc2[4][2] = {};

    for (int c0 = 0; c0 < CH; c0 += 32) {
#pragma unroll
        for (int i = 0; i < 8; i++) {
            int idx = t + i*256;
            int pix = idx >> 5, c = idx & 31;
            As[c][pix] = A[(size_t)(p0 + pix)*CH + c0 + c];
        }
#pragma unroll
        for (int i = 0; i < 8; i++) {
            int idx = t + i*256;
            int o = idx >> 5, c = idx & 31;
            int oo = o0 + o;
            Bs[c][o] = (oo < CH) ? Wp[(size_t)oo*CH + c0 + c] : 0.f;
        }
        __syncthreads();
#pragma unroll
        for (int c = 0; c < 32; c++) {
            ulonglong2 a2 = *(const ulonglong2*)&As[c][tx*4];
            float4 b = *(const float4*)&Bs[c][ty*4];
            ull pb;
            PK2(pb, b.x, b.x); FMA2(acc2[0][0], pb, a2.x); FMA2(acc2[0][1], pb, a2.y);
            PK2(pb, b.y, b.y); FMA2(acc2[1][0], pb, a2.x); FMA2(acc2[1][1], pb, a2.y);
            PK2(pb, b.z, b.z); FMA2(acc2[2][0], pb, a2.x); FMA2(acc2[2][1], pb, a2.y);
            PK2(pb, b.w, b.w); FMA2(acc2[3][0], pb, a2.x); FMA2(acc2[3][1], pb, a2.y);
        }
        __syncthreads();
    }
    float g = gamma[0];
#pragma unroll
    for (int j = 0; j < 4; j++) {
        int o = o0 + ty*4 + j;
        if (o < CH) {
            float a0,a1,a2,a3;
            UPK2(a0,a1,acc2[j][0]);
            UPK2(a2,a3,acc2[j][1]);
            float bb = bp[o];
            size_t base = (size_t)n*CH*HP + (size_t)o*HP + p0 + tx*4;
            float4 xr = *(const float4*)(x + base);
            float4 v;
            v.x = g*(a0 + bb) + xr.x;
            v.y = g*(a1 + bb) + xr.y;
            v.z = g*(a2 + bb) + xr.z;
            v.w = g*(a3 + bb) + xr.w;
            *(float4*)(out + base) = v;
        }
    }
}

// =================================================================================
extern "C" void kernel_launch(void* const* d_in, const int* in_sizes, int n_in,
                              void* d_out, int out_size)
{
    const float* x     = (const float*)d_in[0];
    const float* Wq    = (const float*)d_in[1];
    const float* Wk    = (const float*)d_in[2];
    const float* Wv    = (const float*)d_in[3];
    const float* Wx    = (const float*)d_in[4];
    const float* Wy    = (const float*)d_in[5];
    const float* Wproj = (const float*)d_in[6];
    const float* bproj = (const float*)d_in[7];
    const float* Wc    = (const float*)d_in[8];
    const float* bc    = (const float*)d_in[9];
    const float* gamma = (const float*)d_in[10];
    float* out = (float*)d_out;

    cudaFuncSetAttribute(attn_e_kernel, cudaFuncAttributeMaxDynamicSharedMemorySize,
                         AE_TOT * (int)sizeof(float));

    pf_kernel<<<dim3(2048, 2), 144>>>(Wx, Wy);                 // 1
    qkv_kernel<<<dim3(64, 5, 6), 256>>>(x, Wq, Wk, Wv);        // 2
    bias_kernel<<<dim3(64, NH + 1, 4), 256>>>();               // 3
    attn_e_kernel<<<dim3(HP/TQ, NB), 512,                      // 4  <- ncu window
                    AE_TOT * (int)sizeof(float)>>>(Wc, bc);
    pv_kernel<<<dim3(HP/64, 3, NB), 128>>>();                  // 5
    proj_kernel<<<dim3(64, 5, 2), 256>>>(x, Wproj, bproj, gamma, out);  // 6
}

// round 15
// speedup vs baseline: 1.0119x; 1.0019x over previous
#include <cuda_runtime.h>
#include <math.h>

#define NB  2
#define CH  288
#define HP  4096
#define KPP 1024
#define NH  9
#define DH  32
#define TQ  16

typedef unsigned long long ull;

// ---- packed f32x2 FMA (sm_103a FFMA2; PTX-only path) ----
#define FMA2(d, a, b) asm("fma.rn.f32x2 %0, %1, %2, %0;" : "+l"(d) : "l"(a), "l"(b))
#define PK2(d, lo, hi) asm("mov.b64 %0, {%1, %2};" : "=l"(d) : "r"(__float_as_uint(lo)), "r"(__float_as_uint(hi)))
#define UPK2(lo, hi, v) do { unsigned int _ul, _uh; \
    asm("mov.b64 {%0, %1}, %2;" : "=r"(_ul), "=r"(_uh) : "l"(v)); \
    (lo) = __uint_as_float(_ul); (hi) = __uint_as_float(_uh); } while (0)

// ---- cp.async helpers ----
#define CP_ASYNC16(dst_u32, src_ptr) \
    asm volatile("cp.async.cg.shared.global [%0], [%1], 16;" :: "r"(dst_u32), "l"(src_ptr))
#define CP_COMMIT() asm volatile("cp.async.commit_group;")
#define CP_WAIT(n)  asm volatile("cp.async.wait_group %0;" :: "n"(n))

// ---------------- device scratch ----------------
__device__ float g_Q   [NB*HP*CH];
__device__ float g_KTd [NB*NH*DH*KPP];   // k[n][m][dd][kp]
__device__ float g_V   [NB*KPP*CH];
__device__ float g_O   [NB*HP*CH];
__device__ float g_PFX [NH*64*32*DH];    // pfx[m][a][d][kk]
__device__ float g_PFY [NH*64*32*DH];    // pfy[m][a][d][kk]
__device__ float g_EX  [NB*NH*HP*32];    // ex[n][m][q][wk]
__device__ float g_EY  [NB*NH*HP*32];    // ey[n][m][q][hk]
__device__ float g_Atn [NB*HP*KPP];
__device__ float g_ctxp[NB*32*CH];

// =================================================================================
// Kernel 1: Q/K/V projections.  R9-measured 64x64/4x4 tile.  [unchanged]
// =================================================================================
__global__ __launch_bounds__(256) void qkv_kernel(
    const float* __restrict__ x,
    const float* __restrict__ Wq,
    const float* __restrict__ Wk,
    const float* __restrict__ Wv)
{
    int which = blockIdx.z >> 1;
    int n     = blockIdx.z & 1;
    int rows  = (which == 0) ? HP : KPP;
    int p0    = blockIdx.x * 64;
    if (p0 >= rows) return;
    int o0    = blockIdx.y * 64;

    const float* W = (which == 0) ? Wq : (which == 1 ? Wk : Wv);
    const float* xb = x + (size_t)n*CH*HP;

    __shared__ float As[32][64];
    __shared__ float Bs[32][68];

    int t  = threadIdx.x;
    int tx = t & 15, ty = t >> 4;
    ull acc2[4][2] = {};

    for (int c0 = 0; c0 < CH; c0 += 32) {
#pragma unroll
        for (int i = 0; i < 8; i++) {
            int idx = t + i*256;
            int c = idx >> 6, pix = idx & 63;
            int row = p0 + pix;
            int pixel = (which == 0) ? row : (((row >> 5) << 7) | ((row & 31) << 1));
            As[c][pix] = xb[(size_t)(c0 + c)*HP + pixel];
        }
#pragma unroll
        for (int i = 0; i < 8; i++) {
            int idx = t + i*256;
            int o = idx >> 5, c = idx & 31;
            int oo = o0 + o;
            Bs[c][o] = (oo < CH) ? W[(size_t)oo*CH + c0 + c] : 0.f;
        }
        __syncthreads();
#pragma unroll
        for (int c = 0; c < 32; c++) {
            float4 a = *(const float4*)&As[c][ty*4];
            ulonglong2 b2 = *(const ulonglong2*)&Bs[c][tx*4];
            ull pa;
            PK2(pa, a.x, a.x); FMA2(acc2[0][0], pa, b2.x); FMA2(acc2[0][1], pa, b2.y);
            PK2(pa, a.y, a.y); FMA2(acc2[1][0], pa, b2.x); FMA2(acc2[1][1], pa, b2.y);
            PK2(pa, a.z, a.z); FMA2(acc2[2][0], pa, b2.x); FMA2(acc2[2][1], pa, b2.y);
            PK2(pa, a.w, a.w); FMA2(acc2[3][0], pa, b2.x); FMA2(acc2[3][1], pa, b2.y);
        }
        __syncthreads();
    }
    float acc[4][4];
#pragma unroll
    for (int i = 0; i < 4; i++) {
        UPK2(acc[i][0], acc[i][1], acc2[i][0]);
        UPK2(acc[i][2], acc[i][3], acc2[i][1]);
    }
    int o = o0 + tx*4;
    if (o >= CH) return;

    if (which == 1) {
#pragma unroll
        for (int i = 0; i < 4; i++) {
            int row = p0 + ty*4 + i;
#pragma unroll
            for (int c = 0; c < 4; c++) {
                int oo = o + c;
                g_KTd[(((size_t)n*NH + (oo >> 5))*DH + (oo & 31))*KPP + row] = acc[i][c];
            }
        }
    } else {
        float* out = (which == 0) ? (g_Q + (size_t)n*HP*CH) : (g_V + (size_t)n*KPP*CH);
#pragma unroll
        for (int i = 0; i < 4; i++) {
            int row = p0 + ty*4 + i;
            *(float4*)&out[(size_t)row*CH + o] =
                make_float4(acc[i][0], acc[i][1], acc[i][2], acc[i][3]);
        }
    }
}

// =================================================================================
// Kernel 2: positional factor tables, layout [m][a][d][kk].  [unchanged]
// =================================================================================
__global__ void pf_kernel(const float* __restrict__ Wx, const float* __restrict__ Wy)
{
    int a = blockIdx.x >> 5;
    int b = blockIdx.x & 31;
    const float* W = blockIdx.y ? Wy : Wx;
    float* out = blockIdx.y ? g_PFY : g_PFX;

    __shared__ float emb[144];
    int t = threadIdx.x;
    float diff = (float)a - 2.0f*(float)b;
    if (t < 72) {
        float dm  = powf(1000.0f, (4.0f/288.0f)*(float)t);
        float arg = diff / dm;
        emb[t]      = sinf(arg);
        emb[72 + t] = cosf(arg);
    }
    __syncthreads();
    const float inv_sqrt2 = 0.7071067811865476f;
    for (int j = t; j < CH; j += 144) {
        float s = 0.f;
        const float* wr = W + (size_t)j*144;
#pragma unroll 8
        for (int f = 0; f < 144; f++) s += emb[f]*wr[f];
        int m = j >> 5, dd = j & 31;
        out[(((size_t)m*64 + a)*32 + dd)*32 + b] = s * inv_sqrt2;
    }
}

// =================================================================================
// Kernel 3: bias tables EX/EY + ctx partial sums.  [unchanged]
// =================================================================================
__global__ __launch_bounds__(256) void bias_kernel()
{
    int t = threadIdx.x;
    if (blockIdx.y == NH) {
        if (blockIdx.z >= 2 || blockIdx.x >= 32) return;
        int n = blockIdx.z, b = blockIdx.x;
        for (int c = t; c < CH; c += 256) {
            const float* q = g_Q + ((size_t)n*HP + b*128)*CH + c;
            float s = 0.f;
#pragma unroll 8
            for (int p = 0; p < 128; p++) s += q[(size_t)p*CH];
            g_ctxp[((size_t)n*32 + b)*CH + c] = s;
        }
        return;
    }

    int a   = blockIdx.x;
    int m   = blockIdx.y;
    int n   = blockIdx.z >> 1;
    int isX = blockIdx.z & 1;

    __shared__ float Qs2[32][68];
    __shared__ float Ps[32*32];

    {
        const float* pf = (isX ? g_PFX : g_PFY) + ((size_t)(m*64 + a)*32)*32;
        ((float4*)Ps)[t] = ((const float4*)pf)[t];
    }
    {
        int r = t >> 2, jg = (t & 3) * 8;
        int q = isX ? (r*64 + a) : (a*64 + r);
        const float* qp = g_Q + ((size_t)n*HP + q)*CH + m*DH + jg;
        float4 v0 = *(const float4*)qp;
        float4 v1 = *(const float4*)(qp + 4);
        Qs2[jg+0][r] = v0.x; Qs2[jg+1][r] = v0.y; Qs2[jg+2][r] = v0.z; Qs2[jg+3][r] = v0.w;
        Qs2[jg+4][r] = v1.x; Qs2[jg+5][r] = v1.y; Qs2[jg+6][r] = v1.z; Qs2[jg+7][r] = v1.w;
    }
    __syncthreads();

    int row = t & 63, gk = t >> 6;
    float acc[8] = {};
#pragma unroll
    for (int d = 0; d < 32; d++) {
        float qv = Qs2[d][row];
        float4 pA = *(const float4*)&Ps[d*32 + gk*8];
        float4 pB = *(const float4*)&Ps[d*32 + gk*8 + 4];
        acc[0] += qv*pA.x; acc[1] += qv*pA.y; acc[2] += qv*pA.z; acc[3] += qv*pA.w;
        acc[4] += qv*pB.x; acc[5] += qv*pB.y; acc[6] += qv*pB.z; acc[7] += qv*pB.w;
    }
    int q = isX ? (row*64 + a) : (a*64 + row);
    float* outp = (isX ? g_EX : g_EY) + (((size_t)n*NH + m)*HP + q)*32 + gk*8;
    *(float4*)outp       = make_float4(acc[0], acc[1], acc[2], acc[3]);
    *(float4*)(outp + 4) = make_float4(acc[4], acc[5], acc[6], acc[7]);
}

// =================================================================================
// Kernel 4: attention.  512 threads, 8q x 4 CONTIGUOUS keys per thread
// (one LDS.128 per K row instead of R14's two LDS.64).  cp.async K halves.
// =================================================================================
#define AE_QS  0
#define AE_K0  4608
#define AE_K1  (AE_K0 + 16*1024)
#define AE_EX  (AE_K1 + 16*1024)
#define AE_EY  (AE_EX + 512)
#define AE_RD  (AE_EY + 512)
#define AE_CS  (AE_RD + 256)
#define AE_MX  (AE_CS + 288)
#define AE_TOT (AE_MX + 16)          // 38960 floats = 155,840 B

__device__ __forceinline__ void stage_half(float* buf, const float* kb, int t)
{
    unsigned int dst = (unsigned int)__cvta_generic_to_shared(buf);
#pragma unroll
    for (int i = 0; i < 8; i++) {
        int idx = t + i*512;
        int row = idx >> 8, c4 = (idx & 255)*4;
        CP_ASYNC16(dst + (unsigned int)(row*1024 + c4)*4u, kb + (size_t)row*KPP + c4);
    }
    CP_COMMIT();
}

__global__ __launch_bounds__(512, 1) void attn_e_kernel(
    const float* __restrict__ Wc, const float* __restrict__ bc)
{
    extern __shared__ float sm[];
    float* Qs   = sm + AE_QS;
    float* K0   = sm + AE_K0;
    float* K1   = sm + AE_K1;
    float* exs  = sm + AE_EX;
    float* eys  = sm + AE_EY;
    float* red  = sm + AE_RD;
    float* cs   = sm + AE_CS;
    float* mixs = sm + AE_MX;

    int n  = blockIdx.y;
    int q0 = blockIdx.x * TQ;
    int t  = threadIdx.x;
    int warp = t >> 5, lane = t & 31;

    const float* khead = g_KTd + ((size_t)n*NH)*DH*KPP;

    stage_half(K0, khead, t);
    stage_half(K1, khead + 16*KPP, t);

    if (t < CH) {
        float s = 0.f;
#pragma unroll
        for (int b = 0; b < 32; b++) s += g_ctxp[((size_t)n*32 + b)*CH + t];
        cs[t] = s * (1.0f/HP);
    }

    {
        const float4* src = (const float4*)(g_Q + ((size_t)n*HP + q0)*CH);
        float4* dst = (float4*)Qs;
#pragma unroll
        for (int i = 0; i < 3; i++) {
            int idx = t + i*512;
            if (idx < 1152) dst[idx] = src[idx];
        }
    }
    __syncthreads();
    if (t < NH) {
        float l = bc[t];
        const float* wr = Wc + (size_t)t*CH;
#pragma unroll 8
        for (int o = 0; o < CH; o++) l += cs[o]*wr[o];
        mixs[t] = l;
    }
    __syncthreads();
    if (t == 0) {
        float mx = mixs[0];
        for (int j = 1; j < NH; j++) mx = fmaxf(mx, mixs[j]);
        float sum = 0.f;
        for (int j = 0; j < NH; j++) { float e2 = expf(mixs[j]-mx); mixs[j] = e2; sum += e2; }
        float inv = 1.0f/sum;
        for (int j = 0; j < NH; j++) mixs[j] *= inv;
    }

    const int kt   = t & 255;       // 256 key-threads
    const int kq   = kt * 4;        // 4 CONTIGUOUS keys kq..kq+3
    const int grp  = t >> 8;        // q-group 0/1 (8 queries each)
    const int qb   = grp * 8;
    const int wgrp = warp & 7;      // warp within q-group (8 warps)

    const int wk = kq & 31;         // kq%4==0 -> wk..wk+3 within row (float4 ok)
    const int hk = kq >> 5;         // single h-index for all 4 keys

    float ab[8][4] = {};

    for (int m = 0; m < NH; m++) {
        CP_WAIT(1);
        __syncthreads();   // (1)

        float mw = mixs[m];

        // ---- bias rows: coalesced table loads ----
        {
            const float4* ex = (const float4*)(g_EX + (((size_t)n*NH + m)*HP + q0)*32);
            const float4* ey = (const float4*)(g_EY + (((size_t)n*NH + m)*HP + q0)*32);
            if (t < 128)      ((float4*)exs)[t]       = ex[t];
            else if (t < 256) ((float4*)eys)[t - 128] = ey[t - 128];
        }

        ull acc2[8][2] = {};   // [q][key-pair]: keys kq..kq+1, kq+2..kq+3

        // ---- QK phase A: d = 0..15 from K0 (one LDS.128 per row) ----
#pragma unroll
        for (int d4 = 0; d4 < 4; d4++) {
            const float* kb0 = K0 + (d4*4)*1024;
            ulonglong2 k0 = *(const ulonglong2*)(kb0          + kq);
            ulonglong2 k1 = *(const ulonglong2*)(kb0 + 1024   + kq);
            ulonglong2 k2 = *(const ulonglong2*)(kb0 + 2048   + kq);
            ulonglong2 k3 = *(const ulonglong2*)(kb0 + 3072   + kq);
#pragma unroll
            for (int u = 0; u < 8; u++) {
                float4 qq = *(const float4*)&Qs[(qb+u)*CH + m*DH + d4*4];
                ull pa;
                PK2(pa, qq.x, qq.x); FMA2(acc2[u][0], pa, k0.x); FMA2(acc2[u][1], pa, k0.y);
                PK2(pa, qq.y, qq.y); FMA2(acc2[u][0], pa, k1.x); FMA2(acc2[u][1], pa, k1.y);
                PK2(pa, qq.z, qq.z); FMA2(acc2[u][0], pa, k2.x); FMA2(acc2[u][1], pa, k2.y);
                PK2(pa, qq.w, qq.w); FMA2(acc2[u][0], pa, k3.x); FMA2(acc2[u][1], pa, k3.y);
            }
        }
        __syncthreads();   // (2) done reading K0
        if (m < NH-1) stage_half(K0, khead + (size_t)(m+1)*DH*KPP, t);

        if (m < NH-1) { CP_WAIT(1); } else { CP_WAIT(0); }
        __syncthreads();   // (3) K1 ready

        // ---- QK phase B: d = 16..31 from K1 ----
#pragma unroll
        for (int d4 = 0; d4 < 4; d4++) {
            const float* kb1 = K1 + (d4*4)*1024;
            ulonglong2 k0 = *(const ulonglong2*)(kb1          + kq);
            ulonglong2 k1 = *(const ulonglong2*)(kb1 + 1024   + kq);
            ulonglong2 k2 = *(const ulonglong2*)(kb1 + 2048   + kq);
            ulonglong2 k3 = *(const ulonglong2*)(kb1 + 3072   + kq);
#pragma unroll
            for (int u = 0; u < 8; u++) {
                float4 qq = *(const float4*)&Qs[(qb+u)*CH + m*DH + 16 + d4*4];
                ull pa;
                PK2(pa, qq.x, qq.x); FMA2(acc2[u][0], pa, k0.x); FMA2(acc2[u][1], pa, k0.y);
                PK2(pa, qq.y, qq.y); FMA2(acc2[u][0], pa, k1.x); FMA2(acc2[u][1], pa, k1.y);
                PK2(pa, qq.z, qq.z); FMA2(acc2[u][0], pa, k2.x); FMA2(acc2[u][1], pa, k2.y);
                PK2(pa, qq.w, qq.w); FMA2(acc2[u][0], pa, k3.x); FMA2(acc2[u][1], pa, k3.y);
            }
        }
        __syncthreads();   // (4) done reading K1; exs/eys visible
        if (m < NH-1) stage_half(K1, khead + ((size_t)(m+1)*DH + 16)*KPP, t);

        // ---- bias add (4 contiguous keys) ----
        float e[8][4];
#pragma unroll
        for (int u = 0; u < 8; u++) {
            int qi = qb + u;
            float4 ex4 = *(const float4*)&exs[qi*32 + wk];
            float eyv  = eys[qi*32 + hk];
            float a0,a1;
            UPK2(a0,a1,acc2[u][0]);
            e[u][0] = a0 + ex4.x + eyv;
            e[u][1] = a1 + ex4.y + eyv;
            UPK2(a0,a1,acc2[u][1]);
            e[u][2] = a0 + ex4.z + eyv;
            e[u][3] = a1 + ex4.w + eyv;
        }

        // ---- softmax: 8 warps per q-group ----
        float mx[8];
#pragma unroll
        for (int u = 0; u < 8; u++) {
            float v = fmaxf(fmaxf(e[u][0], e[u][1]), fmaxf(e[u][2], e[u][3]));
#pragma unroll
            for (int s2 = 16; s2; s2 >>= 1) v = fmaxf(v, __shfl_xor_sync(0xffffffffu, v, s2));
            mx[u] = v;
        }
        if (lane == 0) {
#pragma unroll
            for (int u = 0; u < 8; u++) red[grp*64 + wgrp*8 + u] = mx[u];
        }
        __syncthreads();   // (5)
#pragma unroll
        for (int u = 0; u < 8; u++) {
            float v = red[grp*64 + u];
#pragma unroll
            for (int w = 1; w < 8; w++) v = fmaxf(v, red[grp*64 + w*8 + u]);
            mx[u] = v;
        }
        float sme[8];
#pragma unroll
        for (int u = 0; u < 8; u++) {
            float s = 0.f;
#pragma unroll
            for (int j = 0; j < 4; j++) {
                float p = __expf(e[u][j] - mx[u]);
                e[u][j] = p;
                s += p;
            }
#pragma unroll
            for (int s2 = 16; s2; s2 >>= 1) s += __shfl_xor_sync(0xffffffffu, s, s2);
            sme[u] = s;
        }
        if (lane == 0) {
#pragma unroll
            for (int u = 0; u < 8; u++) red[128 + grp*64 + wgrp*8 + u] = sme[u];
        }
        __syncthreads();   // (6)
#pragma unroll
        for (int u = 0; u < 8; u++) {
            float s = red[128 + grp*64 + u];
#pragma unroll
            for (int w = 1; w < 8; w++) s += red[128 + grp*64 + w*8 + u];
            float sc = mw / s;
#pragma unroll
            for (int j = 0; j < 4; j++) ab[u][j] += e[u][j] * sc;
        }
    }

    // ---- write combined attention (one float4 per row) ----
#pragma unroll
    for (int u = 0; u < 8; u++) {
        float* arow = g_Atn + ((size_t)n*HP + q0 + qb + u)*KPP;
        *(float4*)&arow[kq] = make_float4(ab[u][0], ab[u][1], ab[u][2], ab[u][3]);
    }
}

// =================================================================================
// Kernel 5: PV GEMM.  BM=64, BN=96, BK=16, 128 threads, 8x6 per thread.  [unchanged]
// =================================================================================
__global__ __launch_bounds__(128) void pv_kernel()
{
    int n    = blockIdx.z;
    int row0 = blockIdx.x * 64;
    int o0   = blockIdx.y * 96;

    __shared__ float As[16][68];
    __shared__ float Bs[16][96];

    int t  = threadIdx.x;
    int tx = t & 15, ty = t >> 4;

    const float* A = g_Atn + ((size_t)n*HP + row0)*KPP;
    const float* V = g_V + (size_t)n*KPP*CH + o0;

    ull acc2[8][3] = {};

    for (int k0 = 0; k0 < KPP; k0 += 16) {
#pragma unroll
        for (int i = 0; i < 8; i++) {
            int e = t + i*128;
            int row = e >> 4, k = e & 15;
            As[k][row] = A[(size_t)row*KPP + k0 + k];
        }
#pragma unroll
        for (int i = 0; i < 12; i++) {
            int e = t + i*128;
            int k = e / 96, col = e % 96;
            Bs[k][col] = V[(size_t)(k0 + k)*CH + col];
        }
        __syncthreads();
#pragma unroll
        for (int k = 0; k < 16; k++) {
            float4 a0 = *(const float4*)&As[k][ty*8];
            float4 a1 = *(const float4*)&As[k][ty*8 + 4];
            ull b0 = *(const ull*)&Bs[k][tx*6];
            ull b1 = *(const ull*)&Bs[k][tx*6 + 2];
            ull b2 = *(const ull*)&Bs[k][tx*6 + 4];
            ull pa;
            PK2(pa, a0.x, a0.x); FMA2(acc2[0][0],pa,b0); FMA2(acc2[0][1],pa,b1); FMA2(acc2[0][2],pa,b2);
            PK2(pa, a0.y, a0.y); FMA2(acc2[1][0],pa,b0); FMA2(acc2[1][1],pa,b1); FMA2(acc2[1][2],pa,b2);
            PK2(pa, a0.z, a0.z); FMA2(acc2[2][0],pa,b0); FMA2(acc2[2][1],pa,b1); FMA2(acc2[2][2],pa,b2);
            PK2(pa, a0.w, a0.w); FMA2(acc2[3][0],pa,b0); FMA2(acc2[3][1],pa,b1); FMA2(acc2[3][2],pa,b2);
            PK2(pa, a1.x, a1.x); FMA2(acc2[4][0],pa,b0); FMA2(acc2[4][1],pa,b1); FMA2(acc2[4][2],pa,b2);
            PK2(pa, a1.y, a1.y); FMA2(acc2[5][0],pa,b0); FMA2(acc2[5][1],pa,b1); FMA2(acc2[5][2],pa,b2);
            PK2(pa, a1.z, a1.z); FMA2(acc2[6][0],pa,b0); FMA2(acc2[6][1],pa,b1); FMA2(acc2[6][2],pa,b2);
            PK2(pa, a1.w, a1.w); FMA2(acc2[7][0],pa,b0); FMA2(acc2[7][1],pa,b1); FMA2(acc2[7][2],pa,b2);
        }
        __syncthreads();
    }

    float* O = g_O + ((size_t)n*HP + row0)*CH + o0;
#pragma unroll
    for (int i = 0; i < 8; i++) {
        float v0,v1,v2,v3,v4,v5;
        UPK2(v0,v1,acc2[i][0]);
        UPK2(v2,v3,acc2[i][1]);
        UPK2(v4,v5,acc2[i][2]);
        float* orow = O + (size_t)(ty*8 + i)*CH + tx*6;
        *(float2*)&orow[0] = make_float2(v0,v1);
        *(float2*)&orow[2] = make_float2(v2,v3);
        *(float2*)&orow[4] = make_float2(v4,v5);
    }
}

// =================================================================================
// Kernel 6: final projection + residual.  R9 64x64/4x4 tile.  [unchanged]
// =================================================================================
__global__ __launch_bounds__(256) void proj_kernel(
    const float* __restrict__ x,
    const float* __restrict__ Wp,
    const float* __restrict__ bp,
    const float* __restrict__ gamma,
    float* __restrict__ out)
{
    int n  = blockIdx.z;
    int p0 = blockIdx.x * 64;
    int o0 = blockIdx.y * 64;
    const float* A = g_O + (size_t)n*HP*CH;

    __shared__ float As[32][68];
    __shared__ float Bs[32][68];

    int t  = threadIdx.x;
    int tx = t & 15, ty = t >> 4;
    ull acc2[4][2] = {};

    for (int c0 = 0; c0 < CH; c0 += 32) {
#pragma unroll
        for (int i = 0; i < 8; i++) {
            int idx = t + i*256;
            int pix = idx >> 5, c = idx & 31;
            As[c][pix] = A[(size_t)(p0 + pix)*CH + c0 + c];
        }
#pragma unroll
        for (int i = 0; i < 8; i++) {
            int idx = t + i*256;
            int o = idx >> 5, c = idx & 31;
            int oo = o0 + o;
            Bs[c][o] = (oo < CH) ? Wp[(size_t)oo*CH + c0 + c] : 0.f;
        }
        __syncthreads();
#pragma unroll
        for (int c = 0; c < 32; c++) {
            ulonglong2 a2 = *(const ulonglong2*)&As[c][tx*4];
            float4 b = *(const float4*)&Bs[c][ty*4];
            ull pb;
            PK2(pb, b.x, b.x); FMA2(acc2[0][0], pb, a2.x); FMA2(acc2[0][1], pb, a2.y);
            PK2(pb, b.y, b.y); FMA2(acc2[1][0], pb, a2.x); FMA2(acc2[1][1], pb, a2.y);
            PK2(pb, b.z, b.z); FMA2(acc2[2][0], pb, a2.x); FMA2(acc2[2][1], pb, a2.y);
            PK2(pb, b.w, b.w); FMA2(acc2[3][0], pb, a2.x); FMA2(acc2[3][1], pb, a2.y);
        }
        __syncthreads();
    }
    float g = gamma[0];
#pragma unroll
    for (int j = 0; j < 4; j++) {
        int o = o0 + ty*4 + j;
        if (o < CH) {
            float a0,a1,a2,a3;
            UPK2(a0,a1,acc2[j][0]);
            UPK2(a2,a3,acc2[j][1]);
            float bb = bp[o];
            size_t base = (size_t)n*CH*HP + (size_t)o*HP + p0 + tx*4;
            float4 xr = *(const float4*)(x + base);
            float4 v;
            v.x = g*(a0 + bb) + xr.x;
            v.y = g*(a1 + bb) + xr.y;
            v.z = g*(a2 + bb) + xr.z;
            v.w = g*(a3 + bb) + xr.w;
            *(float4*)(out + base) = v;
        }
    }
}

// =================================================================================
extern "C" void kernel_launch(void* const* d_in, const int* in_sizes, int n_in,
                              void* d_out, int out_size)
{
    const float* x     = (const float*)d_in[0];
    const float* Wq    = (const float*)d_in[1];
    const float* Wk    = (const float*)d_in[2];
    const float* Wv    = (const float*)d_in[3];
    const float* Wx    = (const float*)d_in[4];
    const float* Wy    = (const float*)d_in[5];
    const float* Wproj = (const float*)d_in[6];
    const float* bproj = (const float*)d_in[7];
    const float* Wc    = (const float*)d_in[8];
    const float* bc    = (const float*)d_in[9];
    const float* gamma = (const float*)d_in[10];
    float* out = (float*)d_out;

    cudaFuncSetAttribute(attn_e_kernel, cudaFuncAttributeMaxDynamicSharedMemorySize,
                         AE_TOT * (int)sizeof(float));

    pf_kernel<<<dim3(2048, 2), 144>>>(Wx, Wy);                 // 1
    qkv_kernel<<<dim3(64, 5, 6), 256>>>(x, Wq, Wk, Wv);        // 2
    bias_kernel<<<dim3(64, NH + 1, 4), 256>>>();               // 3
    attn_e_kernel<<<dim3(HP/TQ, NB), 512,                      // 4  <- ncu window
                    AE_TOT * (int)sizeof(float)>>>(Wc, bc);
    pv_kernel<<<dim3(HP/64, 3, NB), 128>>>();                  // 5
    proj_kernel<<<dim3(64, 5, 2), 256>>>(x, Wproj, bproj, gamma, out);  // 6
}